// round 1
// baseline (speedup 1.0000x reference)
#include <cuda_runtime.h>
#include <math.h>

#define BATCH 4
#define SEQ   2048
#define EMB   1024
#define NH    16
#define HD    64
#define MROWS (BATCH*SEQ)     /* 8192 */
#define N_QKV (3*EMB)         /* 3072 */

// Scratch (allocation-free rule: __device__ globals)
__device__ float g_q[BATCH*NH*SEQ*HD];
__device__ float g_k[BATCH*NH*SEQ*HD];
__device__ float g_v[BATCH*NH*SEQ*HD];
__device__ float g_o[MROWS*EMB];

// ---------------------------------------------------------------------------
// Tiled SGEMM: C[M,N] = A[M,1024] @ W[1024,N] + bias[N]
// BM=BN=128, BK=16, 256 threads, 8x8 microtile per thread.
// MODE 0: scatter output into g_q/g_k/g_v laid out [B,H,S,D]  (N=3072)
// MODE 1: plain row-major store to C                           (N=1024)
// ---------------------------------------------------------------------------
template<int MODE>
__global__ __launch_bounds__(256)
void gemm_kernel(const float* __restrict__ A,
                 const float* __restrict__ W,
                 const float* __restrict__ bias,
                 float* __restrict__ C,
                 int N)
{
    const int K = EMB;
    __shared__ float As[16][132];   // transposed A tile (pad to soften STS conflicts)
    __shared__ float Bs[16][128];

    const int tid  = threadIdx.x;
    const int bx   = blockIdx.x;    // n-tile
    const int by   = blockIdx.y;    // m-tile
    const int trow = tid >> 4;      // 0..15
    const int tcol = tid & 15;      // 0..15

    const float* Ap = (MODE == 1) ? g_o : A;
    const float* Aptr = Ap + (size_t)(by * 128) * K;
    const float* Wptr = W + bx * 128;

    float acc[8][8];
    #pragma unroll
    for (int i = 0; i < 8; i++)
        #pragma unroll
        for (int j = 0; j < 8; j++) acc[i][j] = 0.f;

    for (int kt = 0; kt < K; kt += 16) {
        // Load A tile (128 rows x 16 k) -> As transposed [k][m]
        #pragma unroll
        for (int p = 0; p < 2; p++) {
            int idx = tid + p * 256;           // 0..511 (512 float4)
            int r   = idx >> 2;                // 0..127
            int c4  = (idx & 3) * 4;           // 0,4,8,12
            float4 av = *(const float4*)(Aptr + (size_t)r * K + kt + c4);
            As[c4 + 0][r] = av.x;
            As[c4 + 1][r] = av.y;
            As[c4 + 2][r] = av.z;
            As[c4 + 3][r] = av.w;
            // Load B tile (16 k-rows x 128 cols)
            int br  = idx >> 5;                // 0..15
            int bc4 = (idx & 31) * 4;          // 0..124
            float4 bv = *(const float4*)(Wptr + (size_t)(kt + br) * N + bc4);
            *(float4*)&Bs[br][bc4] = bv;
        }
        __syncthreads();

        #pragma unroll
        for (int k = 0; k < 16; k++) {
            float a[8], b[8];
            #pragma unroll
            for (int i = 0; i < 8; i++) a[i] = As[k][trow * 8 + i];
            #pragma unroll
            for (int j = 0; j < 8; j++) b[j] = Bs[k][tcol * 8 + j];
            #pragma unroll
            for (int i = 0; i < 8; i++)
                #pragma unroll
                for (int j = 0; j < 8; j++)
                    acc[i][j] = fmaf(a[i], b[j], acc[i][j]);
        }
        __syncthreads();
    }

    // Epilogue
    #pragma unroll
    for (int i = 0; i < 8; i++) {
        int m = by * 128 + trow * 8 + i;
        int b = m / SEQ, s = m % SEQ;
        #pragma unroll
        for (int j = 0; j < 8; j++) {
            int n = bx * 128 + tcol * 8 + j;
            float v = acc[i][j] + bias[n];
            if (MODE == 0) {
                int cls = n >> 10;             // n / 1024
                int r   = n & 1023;
                int h   = r >> 6;              // / 64
                int d   = r & 63;
                float* dst = (cls == 0) ? g_q : (cls == 1) ? g_k : g_v;
                dst[((size_t)((b * NH) + h) * SEQ + s) * HD + d] = v;
            } else {
                C[(size_t)m * N + n] = v;
            }
        }
    }
}

// ---------------------------------------------------------------------------
// Flash-attention style: 1 query row per thread, K/V tiles of 32 in smem,
// online softmax, fp32 exact. Output written in [B,S,E] layout to g_o.
// grid = (SEQ/128, NH, BATCH), block = 128
// ---------------------------------------------------------------------------
__global__ __launch_bounds__(128)
void attn_kernel()
{
    const int b = blockIdx.z;
    const int h = blockIdx.y;
    const int qrow = blockIdx.x * 128 + threadIdx.x;

    const float* Qp = g_q + (size_t)((b * NH) + h) * SEQ * HD;
    const float* Kp = g_k + (size_t)((b * NH) + h) * SEQ * HD;
    const float* Vp = g_v + (size_t)((b * NH) + h) * SEQ * HD;

    __shared__ float Ks[32][HD];
    __shared__ float Vs[32][HD];

    float q[HD];
    #pragma unroll
    for (int d = 0; d < HD; d += 4) {
        float4 t = *(const float4*)(Qp + (size_t)qrow * HD + d);
        q[d + 0] = t.x * 0.125f;   // 1/sqrt(64)
        q[d + 1] = t.y * 0.125f;
        q[d + 2] = t.z * 0.125f;
        q[d + 3] = t.w * 0.125f;
    }

    float o[HD];
    #pragma unroll
    for (int d = 0; d < HD; d++) o[d] = 0.f;
    float m_i = -1e30f, l = 0.f;

    for (int kt = 0; kt < SEQ; kt += 32) {
        // Stage K/V tile: 32x64 floats each = 512 float4 each
        #pragma unroll
        for (int p = 0; p < 4; p++) {
            int idx = threadIdx.x + p * 128;   // 0..511
            int r   = idx >> 4;                // 0..31
            int c4  = (idx & 15) * 4;          // 0..60
            *(float4*)&Ks[r][c4] = *(const float4*)(Kp + (size_t)(kt + r) * HD + c4);
            *(float4*)&Vs[r][c4] = *(const float4*)(Vp + (size_t)(kt + r) * HD + c4);
        }
        __syncthreads();

        float sc[32];
        #pragma unroll
        for (int j = 0; j < 32; j++) {
            float a0 = 0.f, a1 = 0.f, a2 = 0.f, a3 = 0.f;
            #pragma unroll
            for (int d = 0; d < HD; d += 4) {
                a0 = fmaf(q[d + 0], Ks[j][d + 0], a0);
                a1 = fmaf(q[d + 1], Ks[j][d + 1], a1);
                a2 = fmaf(q[d + 2], Ks[j][d + 2], a2);
                a3 = fmaf(q[d + 3], Ks[j][d + 3], a3);
            }
            sc[j] = (a0 + a1) + (a2 + a3);
        }

        float mt = m_i;
        #pragma unroll
        for (int j = 0; j < 32; j++) mt = fmaxf(mt, sc[j]);

        float alpha = __expf(m_i - mt);
        l *= alpha;
        #pragma unroll
        for (int d = 0; d < HD; d++) o[d] *= alpha;

        #pragma unroll
        for (int j = 0; j < 32; j++) {
            float p = __expf(sc[j] - mt);
            l += p;
            #pragma unroll
            for (int d = 0; d < HD; d++)
                o[d] = fmaf(p, Vs[j][d], o[d]);
        }
        m_i = mt;
        __syncthreads();
    }

    float inv = 1.f / l;
    float* dst = g_o + (size_t)(b * SEQ + qrow) * EMB + h * HD;
    #pragma unroll
    for (int d = 0; d < HD; d += 4) {
        float4 t;
        t.x = o[d + 0] * inv;
        t.y = o[d + 1] * inv;
        t.z = o[d + 2] * inv;
        t.w = o[d + 3] * inv;
        *(float4*)&dst[d] = t;
    }
}

extern "C" void kernel_launch(void* const* d_in, const int* in_sizes, int n_in,
                              void* d_out, int out_size)
{
    const float* x      = (const float*)d_in[0];
    const float* w_qkv  = (const float*)d_in[1];
    const float* b_qkv  = (const float*)d_in[2];
    const float* w_proj = (const float*)d_in[3];
    const float* b_proj = (const float*)d_in[4];
    float* out = (float*)d_out;

    // 1) QKV projection -> scatter to g_q/g_k/g_v [B,H,S,D]
    {
        dim3 grid(N_QKV / 128, MROWS / 128);
        gemm_kernel<0><<<grid, 256>>>(x, w_qkv, b_qkv, nullptr, N_QKV);
    }
    // 2) Attention -> g_o [B,S,E]
    {
        dim3 grid(SEQ / 128, NH, BATCH);
        attn_kernel<<<grid, 128>>>();
    }
    // 3) Output projection -> d_out
    {
        dim3 grid(EMB / 128, MROWS / 128);
        gemm_kernel<1><<<grid, 256>>>(nullptr, w_proj, b_proj, out, EMB);
    }
}

// round 2
// speedup vs baseline: 3.9925x; 3.9925x over previous
#include <cuda_runtime.h>
#include <math.h>
#include <stdint.h>

#define BATCH 4
#define SEQ   2048
#define EMB   1024
#define NH    16
#define HD    64
#define MROWS (BATCH*SEQ)     /* 8192 */
#define N_QKV (3*EMB)         /* 3072 */

// Scratch (allocation-free rule: __device__ globals)
__device__ float g_q[BATCH*NH*SEQ*HD];
__device__ float g_k[BATCH*NH*SEQ*HD];
__device__ float g_v[BATCH*NH*SEQ*HD];
__device__ float g_o[MROWS*EMB];

// ---------------------------------------------------------------------------
// helpers
// ---------------------------------------------------------------------------
__device__ __forceinline__ float tf32r(float x) {
    uint32_t u;
    asm("cvt.rna.tf32.f32 %0, %1;" : "=r"(u) : "f"(x));
    return __uint_as_float(u);
}
__device__ __forceinline__ uint32_t fb(float x) { return __float_as_uint(x); }

__device__ __forceinline__ void mma8(float* c, const uint32_t* a, const uint32_t* b) {
    asm volatile(
        "mma.sync.aligned.m16n8k8.row.col.f32.tf32.tf32.f32 "
        "{%0,%1,%2,%3},{%4,%5,%6,%7},{%8,%9},{%0,%1,%2,%3};\n"
        : "+f"(c[0]), "+f"(c[1]), "+f"(c[2]), "+f"(c[3])
        : "r"(a[0]), "r"(a[1]), "r"(a[2]), "r"(a[3]), "r"(b[0]), "r"(b[1]));
}

// ---------------------------------------------------------------------------
// TF32 tensor-core GEMM: C[M,N] = A[M,1024] @ W[1024,N] + bias
// BM=128,BN=128,BK=32, 256 threads (8 warps, 2x4), warp tile 64x32
// MODE 0: scatter into g_q/g_k/g_v [B,H,S,D]; MODE 1: row-major store to C
// ---------------------------------------------------------------------------
#define PA 36    /* As row stride: bank = 4g+t4, conflict-free frags */
#define PB 136   /* Bs row stride: bank = 8t4+g, conflict-free frags */

template<int MODE>
__global__ __launch_bounds__(256)
void gemm_tc(const float* __restrict__ A,
             const float* __restrict__ W,
             const float* __restrict__ bias,
             float* __restrict__ C,
             int N)
{
    __shared__ float As[128 * PA];  // [m][k]
    __shared__ float Bs[32 * PB];   // [k][n]

    const int tid  = threadIdx.x;
    const int warp = tid >> 5, lane = tid & 31;
    const int g = lane >> 2, t4 = lane & 3;
    const int wm = (warp >> 2) * 64, wn = (warp & 3) * 32;
    const int bx = blockIdx.x, by = blockIdx.y;

    const float* Ap = (MODE == 1) ? g_o : A;
    const float* Abase = Ap + (size_t)(by * 128) * 1024;
    const float* Wbase = W + bx * 128;

    float acc[4][4][4];
    #pragma unroll
    for (int i = 0; i < 4; i++)
        #pragma unroll
        for (int j = 0; j < 4; j++)
            #pragma unroll
            for (int c = 0; c < 4; c++) acc[i][j][c] = 0.f;

    for (int kt = 0; kt < 1024; kt += 32) {
        // A tile 128x32: 1024 float4, 4/thread
        #pragma unroll
        for (int p = 0; p < 4; p++) {
            int idx = tid + p * 256;
            int r = idx >> 3, c4 = (idx & 7) * 4;
            float4 v = *(const float4*)(Abase + (size_t)r * 1024 + kt + c4);
            v.x = tf32r(v.x); v.y = tf32r(v.y); v.z = tf32r(v.z); v.w = tf32r(v.w);
            *(float4*)&As[r * PA + c4] = v;
        }
        // B tile 32x128: 1024 float4, 4/thread
        #pragma unroll
        for (int p = 0; p < 4; p++) {
            int idx = tid + p * 256;
            int kr = idx >> 5, n4 = (idx & 31) * 4;
            float4 v = *(const float4*)(Wbase + (size_t)(kt + kr) * N + n4);
            v.x = tf32r(v.x); v.y = tf32r(v.y); v.z = tf32r(v.z); v.w = tf32r(v.w);
            *(float4*)&Bs[kr * PB + n4] = v;
        }
        __syncthreads();

        #pragma unroll
        for (int ks = 0; ks < 4; ks++) {
            const int k0 = ks * 8;
            uint32_t a[4][4], b[4][2];
            #pragma unroll
            for (int i = 0; i < 4; i++) {
                int m0 = wm + i * 16;
                a[i][0] = fb(As[(m0 + g)     * PA + k0 + t4]);
                a[i][1] = fb(As[(m0 + g + 8) * PA + k0 + t4]);
                a[i][2] = fb(As[(m0 + g)     * PA + k0 + t4 + 4]);
                a[i][3] = fb(As[(m0 + g + 8) * PA + k0 + t4 + 4]);
            }
            #pragma unroll
            for (int j = 0; j < 4; j++) {
                int n0 = wn + j * 8;
                b[j][0] = fb(Bs[(k0 + t4)     * PB + n0 + g]);
                b[j][1] = fb(Bs[(k0 + t4 + 4) * PB + n0 + g]);
            }
            #pragma unroll
            for (int i = 0; i < 4; i++)
                #pragma unroll
                for (int j = 0; j < 4; j++)
                    mma8(acc[i][j], a[i], b[j]);
        }
        __syncthreads();
    }

    // Epilogue
    #pragma unroll
    for (int i = 0; i < 4; i++) {
        #pragma unroll
        for (int j = 0; j < 4; j++) {
            #pragma unroll
            for (int c = 0; c < 4; c++) {
                int m = by * 128 + wm + i * 16 + g + ((c >= 2) ? 8 : 0);
                int n = bx * 128 + wn + j * 8 + 2 * t4 + (c & 1);
                float v = acc[i][j][c] + bias[n];
                if (MODE == 0) {
                    int bb = m / SEQ, s = m % SEQ;
                    int cls = n >> 10;
                    int r   = n & 1023;
                    int h   = r >> 6;
                    int d   = r & 63;
                    float* dst = (cls == 0) ? g_q : (cls == 1) ? g_k : g_v;
                    dst[((size_t)((bb * NH) + h) * SEQ + s) * HD + d] = v;
                } else {
                    C[(size_t)m * N + n] = v;
                }
            }
        }
    }
}

// ---------------------------------------------------------------------------
// Flash attention with tf32 tensor cores.
// Block: 256 threads (8 warps), q-tile 128 (16 rows/warp), kv-tile 64.
// S = Q@K^T via mma (A=Qs[m][d], B=Ks[kv][d]); online softmax in C-fragments;
// P staged through smem; O += P@V via mma (A=Ps[m][kv], B=Vs[kv][d]).
// ---------------------------------------------------------------------------
#define PQ 68   /* Qs/Ks/Ps stride: bank = 4g+t4 / etc, conflict-free frags */
#define PV 72   /* Vs stride: bank = 8t4+g, conflict-free */

__global__ __launch_bounds__(256)
void attn_tc()
{
    extern __shared__ float sm[];
    float* Qs = sm;                     // 128 x PQ  [m][d]
    float* Ks = Qs + 128 * PQ;          // 64  x PQ  [kv][d]
    float* Vs = Ks + 64 * PQ;           // 64  x PV  [kv][d]
    float* Ps = Vs + 64 * PV;           // 128 x PQ  [m][kv]

    const int b = blockIdx.z;
    const int h = blockIdx.y;
    const int q0 = blockIdx.x * 128;

    const int tid  = threadIdx.x;
    const int warp = tid >> 5, lane = tid & 31;
    const int g = lane >> 2, t4 = lane & 3;
    const int m0 = warp * 16;

    const size_t bh = (size_t)(b * NH + h) * SEQ * HD;
    const float* Qp = g_q + bh;
    const float* Kp = g_k + bh;
    const float* Vp = g_v + bh;

    // Load Q tile (scaled by 1/sqrt(64), tf32-rounded): 2048 float4, 8/thread
    #pragma unroll
    for (int p = 0; p < 8; p++) {
        int idx = tid + p * 256;
        int r = idx >> 4, d4 = (idx & 15) * 4;
        float4 v = *(const float4*)(Qp + (size_t)(q0 + r) * HD + d4);
        v.x = tf32r(v.x * 0.125f); v.y = tf32r(v.y * 0.125f);
        v.z = tf32r(v.z * 0.125f); v.w = tf32r(v.w * 0.125f);
        *(float4*)&Qs[r * PQ + d4] = v;
    }

    float oacc[8][4];
    #pragma unroll
    for (int j = 0; j < 8; j++)
        #pragma unroll
        for (int c = 0; c < 4; c++) oacc[j][c] = 0.f;
    float mrow0 = -1e30f, mrow1 = -1e30f, lrow0 = 0.f, lrow1 = 0.f;

    for (int kt = 0; kt < SEQ; kt += 64) {
        __syncthreads();   // prior iteration's reads of Ks/Vs complete
        // Load K/V tiles (64x64): 1024 float4 each, 4/thread each
        #pragma unroll
        for (int p = 0; p < 4; p++) {
            int idx = tid + p * 256;
            int r = idx >> 4, d4 = (idx & 15) * 4;
            float4 kv4 = *(const float4*)(Kp + (size_t)(kt + r) * HD + d4);
            kv4.x = tf32r(kv4.x); kv4.y = tf32r(kv4.y);
            kv4.z = tf32r(kv4.z); kv4.w = tf32r(kv4.w);
            *(float4*)&Ks[r * PQ + d4] = kv4;
            float4 vv4 = *(const float4*)(Vp + (size_t)(kt + r) * HD + d4);
            vv4.x = tf32r(vv4.x); vv4.y = tf32r(vv4.y);
            vv4.z = tf32r(vv4.z); vv4.w = tf32r(vv4.w);
            *(float4*)&Vs[r * PV + d4] = vv4;
        }
        __syncthreads();

        // ---- S = Q @ K^T  (warp tile 16 x 64) ----
        float s[8][4];
        #pragma unroll
        for (int j = 0; j < 8; j++)
            #pragma unroll
            for (int c = 0; c < 4; c++) s[j][c] = 0.f;

        #pragma unroll
        for (int ks = 0; ks < 8; ks++) {
            const int k0 = ks * 8;
            uint32_t a[4];
            a[0] = fb(Qs[(m0 + g)     * PQ + k0 + t4]);
            a[1] = fb(Qs[(m0 + g + 8) * PQ + k0 + t4]);
            a[2] = fb(Qs[(m0 + g)     * PQ + k0 + t4 + 4]);
            a[3] = fb(Qs[(m0 + g + 8) * PQ + k0 + t4 + 4]);
            #pragma unroll
            for (int j = 0; j < 8; j++) {
                uint32_t bfr[2];
                bfr[0] = fb(Ks[(j * 8 + g) * PQ + k0 + t4]);
                bfr[1] = fb(Ks[(j * 8 + g) * PQ + k0 + t4 + 4]);
                mma8(s[j], a, bfr);
            }
        }

        // ---- online softmax (rows g and g+8 of this warp's 16-row tile) ----
        float tmax0 = -1e30f, tmax1 = -1e30f;
        #pragma unroll
        for (int j = 0; j < 8; j++) {
            tmax0 = fmaxf(tmax0, fmaxf(s[j][0], s[j][1]));
            tmax1 = fmaxf(tmax1, fmaxf(s[j][2], s[j][3]));
        }
        tmax0 = fmaxf(tmax0, __shfl_xor_sync(0xffffffffu, tmax0, 1));
        tmax0 = fmaxf(tmax0, __shfl_xor_sync(0xffffffffu, tmax0, 2));
        tmax1 = fmaxf(tmax1, __shfl_xor_sync(0xffffffffu, tmax1, 1));
        tmax1 = fmaxf(tmax1, __shfl_xor_sync(0xffffffffu, tmax1, 2));

        float newm0 = fmaxf(mrow0, tmax0);
        float newm1 = fmaxf(mrow1, tmax1);
        float alpha0 = __expf(mrow0 - newm0);
        float alpha1 = __expf(mrow1 - newm1);

        float sum0 = 0.f, sum1 = 0.f;
        #pragma unroll
        for (int j = 0; j < 8; j++) {
            s[j][0] = __expf(s[j][0] - newm0);
            s[j][1] = __expf(s[j][1] - newm0);
            s[j][2] = __expf(s[j][2] - newm1);
            s[j][3] = __expf(s[j][3] - newm1);
            sum0 += s[j][0] + s[j][1];
            sum1 += s[j][2] + s[j][3];
        }
        sum0 += __shfl_xor_sync(0xffffffffu, sum0, 1);
        sum0 += __shfl_xor_sync(0xffffffffu, sum0, 2);
        sum1 += __shfl_xor_sync(0xffffffffu, sum1, 1);
        sum1 += __shfl_xor_sync(0xffffffffu, sum1, 2);

        lrow0 = lrow0 * alpha0 + sum0;
        lrow1 = lrow1 * alpha1 + sum1;
        mrow0 = newm0; mrow1 = newm1;

        #pragma unroll
        for (int j = 0; j < 8; j++) {
            oacc[j][0] *= alpha0; oacc[j][1] *= alpha0;
            oacc[j][2] *= alpha1; oacc[j][3] *= alpha1;
        }

        // ---- stage P to smem (tf32) ----
        #pragma unroll
        for (int j = 0; j < 8; j++) {
            int col = j * 8 + 2 * t4;
            Ps[(m0 + g)     * PQ + col]     = tf32r(s[j][0]);
            Ps[(m0 + g)     * PQ + col + 1] = tf32r(s[j][1]);
            Ps[(m0 + g + 8) * PQ + col]     = tf32r(s[j][2]);
            Ps[(m0 + g + 8) * PQ + col + 1] = tf32r(s[j][3]);
        }
        __syncwarp();

        // ---- O += P @ V ----
        #pragma unroll
        for (int ks = 0; ks < 8; ks++) {
            const int k0 = ks * 8;
            uint32_t a[4];
            a[0] = fb(Ps[(m0 + g)     * PQ + k0 + t4]);
            a[1] = fb(Ps[(m0 + g + 8) * PQ + k0 + t4]);
            a[2] = fb(Ps[(m0 + g)     * PQ + k0 + t4 + 4]);
            a[3] = fb(Ps[(m0 + g + 8) * PQ + k0 + t4 + 4]);
            #pragma unroll
            for (int j = 0; j < 8; j++) {
                uint32_t bfr[2];
                bfr[0] = fb(Vs[(k0 + t4)     * PV + j * 8 + g]);
                bfr[1] = fb(Vs[(k0 + t4 + 4) * PV + j * 8 + g]);
                mma8(oacc[j], a, bfr);
            }
        }
    }

    // ---- write O (normalized) in [B,S,E] layout ----
    float inv0 = 1.f / lrow0;
    float inv1 = 1.f / lrow1;
    const int row0 = q0 + m0 + g;
    const int row1 = row0 + 8;
    float* dst0 = g_o + (size_t)(b * SEQ + row0) * EMB + h * HD;
    float* dst1 = g_o + (size_t)(b * SEQ + row1) * EMB + h * HD;
    #pragma unroll
    for (int j = 0; j < 8; j++) {
        int col = j * 8 + 2 * t4;
        dst0[col]     = oacc[j][0] * inv0;
        dst0[col + 1] = oacc[j][1] * inv0;
        dst1[col]     = oacc[j][2] * inv1;
        dst1[col + 1] = oacc[j][3] * inv1;
    }
}

// ---------------------------------------------------------------------------
extern "C" void kernel_launch(void* const* d_in, const int* in_sizes, int n_in,
                              void* d_out, int out_size)
{
    const float* x      = (const float*)d_in[0];
    const float* w_qkv  = (const float*)d_in[1];
    const float* b_qkv  = (const float*)d_in[2];
    const float* w_proj = (const float*)d_in[3];
    const float* b_proj = (const float*)d_in[4];
    float* out = (float*)d_out;

    const int attn_smem = (128 * PQ + 64 * PQ + 64 * PV + 128 * PQ) * 4; // 105,472 B
    cudaFuncSetAttribute(attn_tc, cudaFuncAttributeMaxDynamicSharedMemorySize, attn_smem);

    // 1) QKV projection -> g_q/g_k/g_v [B,H,S,D]
    {
        dim3 grid(N_QKV / 128, MROWS / 128);
        gemm_tc<0><<<grid, 256>>>(x, w_qkv, b_qkv, nullptr, N_QKV);
    }
    // 2) Attention -> g_o [B,S,E]
    {
        dim3 grid(SEQ / 128, NH, BATCH);
        attn_tc<<<grid, 256, attn_smem>>>();
    }
    // 3) Output projection -> d_out
    {
        dim3 grid(EMB / 128, MROWS / 128);
        gemm_tc<1><<<grid, 256>>>(nullptr, w_proj, b_proj, out, EMB);
    }
}

// round 4
// speedup vs baseline: 8.5591x; 2.1438x over previous
#include <cuda_runtime.h>
#include <cuda_fp16.h>
#include <math.h>
#include <stdint.h>

#define BATCH 4
#define SEQ   2048
#define EMB   1024
#define NH    16
#define HD    64
#define MROWS (BATCH*SEQ)     /* 8192 */
#define N_QKV (3*EMB)         /* 3072 */

// fp16 scratch (allocation-free rule: __device__ globals)
__device__ __half gx16[MROWS*EMB];
__device__ __half gw16[EMB*N_QKV];
__device__ __half gwp16[EMB*EMB];
__device__ __half g_q16[BATCH*NH*SEQ*HD];
__device__ __half g_k16[BATCH*NH*SEQ*HD];
__device__ __half g_v16[BATCH*NH*SEQ*HD];
__device__ __half g_o16[MROWS*EMB];

// ---------------------------------------------------------------------------
// helpers
// ---------------------------------------------------------------------------
__device__ __forceinline__ uint32_t smem_u32(const void* p) {
    uint32_t a;
    asm("{ .reg .u64 t; cvta.to.shared.u64 t, %1; cvt.u32.u64 %0, t; }"
        : "=r"(a) : "l"(p));
    return a;
}
#define CP16(dst, src) \
    asm volatile("cp.async.cg.shared.global [%0], [%1], 16;" :: "r"(dst), "l"(src))
#define CP_COMMIT() asm volatile("cp.async.commit_group;")
#define CP_WAIT0()  asm volatile("cp.async.wait_group 0;")
#define CP_WAIT1()  asm volatile("cp.async.wait_group 1;")

__device__ __forceinline__ void ldsm4(uint32_t* r, uint32_t addr) {
    asm volatile("ldmatrix.sync.aligned.m8n8.x4.shared.b16 {%0,%1,%2,%3}, [%4];"
        : "=r"(r[0]), "=r"(r[1]), "=r"(r[2]), "=r"(r[3]) : "r"(addr));
}
__device__ __forceinline__ void ldsm4t(uint32_t* r, uint32_t addr) {
    asm volatile("ldmatrix.sync.aligned.m8n8.x4.trans.shared.b16 {%0,%1,%2,%3}, [%4];"
        : "=r"(r[0]), "=r"(r[1]), "=r"(r[2]), "=r"(r[3]) : "r"(addr));
}
__device__ __forceinline__ void mma16(float* c, const uint32_t* a, const uint32_t* b) {
    asm volatile(
        "mma.sync.aligned.m16n8k16.row.col.f32.f16.f16.f32 "
        "{%0,%1,%2,%3},{%4,%5,%6,%7},{%8,%9},{%0,%1,%2,%3};\n"
        : "+f"(c[0]), "+f"(c[1]), "+f"(c[2]), "+f"(c[3])
        : "r"(a[0]), "r"(a[1]), "r"(a[2]), "r"(a[3]), "r"(b[0]), "r"(b[1]));
}
__device__ __forceinline__ uint32_t packh2(float x, float y) {
    __half2 h = __floats2half2_rn(x, y);
    return *(uint32_t*)&h;
}

// ---------------------------------------------------------------------------
// fp32 -> fp16 conversion (grid-stride over float4)
// ---------------------------------------------------------------------------
__global__ void cvt4(const float* __restrict__ src, __half* __restrict__ dst, int n4)
{
    for (int i = blockIdx.x * blockDim.x + threadIdx.x; i < n4; i += gridDim.x * blockDim.x) {
        float4 v = *(const float4*)(src + 4 * i);
        uint2 o;
        o.x = packh2(v.x, v.y);
        o.y = packh2(v.z, v.w);
        *(uint2*)(dst + 4 * i) = o;
    }
}

// ---------------------------------------------------------------------------
// fp16 HMMA GEMM: C[M,N] = A[M,1024] @ W[1024,N] + bias
// BM=128, BN=128, BK=32, 256 threads (8 warps, 2x4), warp tile 64x32,
// cp.async double-buffered.  A smem [m][k] stride 40, W smem [k][n] stride 136.
// MODE 0: scatter fp16 into g_q16/g_k16/g_v16 [B,H,S,D]; MODE 1: fp32 store.
// ---------------------------------------------------------------------------
#define SA 40
#define SB 136
#define ABUF (128*SA)   /* halves per A buffer */
#define BBUF (32*SB)

template<int MODE>
__global__ __launch_bounds__(256)
void gemm_h(const __half* __restrict__ Ag,
            const __half* __restrict__ W,
            const float* __restrict__ bias,
            float* __restrict__ C,
            int N)
{
    __shared__ __half As[2][ABUF];
    __shared__ __half Bs[2][BBUF];

    const int tid  = threadIdx.x;
    const int warp = tid >> 5, lane = tid & 31;
    const int g = lane >> 2, t4 = lane & 3;
    const int r8 = lane & 7, mt = lane >> 3;
    const int wm = (warp >> 2) * 64, wn = (warp & 3) * 32;
    const int bx = blockIdx.x, by = blockIdx.y;

    const __half* Ab = Ag + (size_t)(by * 128) * 1024;
    const __half* Wb = W + bx * 128;

    const uint32_t a_sm = smem_u32(&As[0][0]);
    const uint32_t b_sm = smem_u32(&Bs[0][0]);

    // staging indices
    const int a_row = tid >> 1;                    // chunks tid, tid+256 -> rows
    float acc[4][4][4];
    #pragma unroll
    for (int i = 0; i < 4; i++)
        #pragma unroll
        for (int j = 0; j < 4; j++)
            #pragma unroll
            for (int c = 0; c < 4; c++) acc[i][j][c] = 0.f;

    // ---- stage tile kt into buffer s ----
    auto stage = [&](int s, int kt) {
        #pragma unroll
        for (int p = 0; p < 2; p++) {
            int c = tid + p * 256;
            int row = c >> 2, cc = c & 3;
            const __half* src = Ab + (size_t)row * 1024 + kt * 32 + cc * 8;
            CP16(a_sm + (s * ABUF + row * SA + cc * 8) * 2, src);
        }
        #pragma unroll
        for (int p = 0; p < 2; p++) {
            int c = tid + p * 256;
            int kr = c >> 4, nc = c & 15;
            const __half* src = Wb + (size_t)(kt * 32 + kr) * N + nc * 8;
            CP16(b_sm + (s * BBUF + kr * SB + nc * 8) * 2, src);
        }
    };

    stage(0, 0);
    CP_COMMIT();

    for (int kt = 0; kt < 32; kt++) {
        if (kt < 31) { stage((kt + 1) & 1, kt + 1); CP_COMMIT(); CP_WAIT1(); }
        else         { CP_WAIT0(); }
        __syncthreads();

        const int s = kt & 1;
        const uint32_t ab = a_sm + s * ABUF * 2;
        const uint32_t bb = b_sm + s * BBUF * 2;
        #pragma unroll
        for (int ks = 0; ks < 2; ks++) {
            const int k0 = ks * 16;
            uint32_t a[4][4];
            #pragma unroll
            for (int i = 0; i < 4; i++)
                ldsm4(a[i], ab + ((wm + i * 16 + (mt & 1) * 8 + r8) * SA
                                  + k0 + (mt >> 1) * 8) * 2);
            uint32_t b[2][4];
            #pragma unroll
            for (int j2 = 0; j2 < 2; j2++)
                ldsm4t(b[j2], bb + ((k0 + (mt & 1) * 8 + r8) * SB
                                    + wn + j2 * 16 + (mt >> 1) * 8) * 2);
            #pragma unroll
            for (int i = 0; i < 4; i++)
                #pragma unroll
                for (int j = 0; j < 4; j++)
                    mma16(acc[i][j], a[i], &b[j >> 1][(j & 1) * 2]);
        }
        __syncthreads();
    }

    // ---- epilogue ----
    #pragma unroll
    for (int i = 0; i < 4; i++) {
        #pragma unroll
        for (int j = 0; j < 4; j++) {
            const int m = by * 128 + wm + i * 16 + g;
            const int n = bx * 128 + wn + j * 8 + 2 * t4;
            const float bn0 = bias[n], bn1 = bias[n + 1];
            float v00 = acc[i][j][0] + bn0, v01 = acc[i][j][1] + bn1;  // row m
            float v10 = acc[i][j][2] + bn0, v11 = acc[i][j][3] + bn1;  // row m+8
            if (MODE == 0) {
                const int cls = n >> 10, rr = n & 1023;
                const int hh = rr >> 6, d = rr & 63;
                __half* base = (cls == 0) ? g_q16 : (cls == 1) ? g_k16 : g_v16;
                const int b0 = m >> 11, s0 = m & 2047;
                const int b1 = (m + 8) >> 11, s1 = (m + 8) & 2047;
                __half2 h0 = __floats2half2_rn(v00, v01);
                __half2 h1 = __floats2half2_rn(v10, v11);
                *(__half2*)(base + ((size_t)(b0 * NH + hh) * SEQ + s0) * HD + d) = h0;
                *(__half2*)(base + ((size_t)(b1 * NH + hh) * SEQ + s1) * HD + d) = h1;
            } else {
                float2 f0 = make_float2(v00, v01);
                float2 f1 = make_float2(v10, v11);
                *(float2*)(C + (size_t)m * N + n) = f0;
                *(float2*)(C + (size_t)(m + 8) * N + n) = f1;
            }
        }
    }
}

// ---------------------------------------------------------------------------
// fp16 flash attention. 256 threads (8 warps), q-tile 128 (16 rows/warp),
// kv-tile 64, cp.async double-buffered K/V, register-resident P.
// ---------------------------------------------------------------------------
#define SQ 72
#define KBUF (64*SQ)
#define ATTN_SMEM ((128*SQ + 4*KBUF) * 2)   /* bytes = 55296 */

__global__ __launch_bounds__(256)
void attn_h()
{
    extern __shared__ __half smh[];
    __half* Qs = smh;                 // 128 x SQ
    __half* Ks = Qs + 128 * SQ;       // 2 x 64 x SQ
    __half* Vs = Ks + 2 * KBUF;       // 2 x 64 x SQ

    const int b = blockIdx.z;
    const int h = blockIdx.y;
    const int q0 = blockIdx.x * 128;

    const int tid  = threadIdx.x;
    const int warp = tid >> 5, lane = tid & 31;
    const int g = lane >> 2, t4 = lane & 3;
    const int r8 = lane & 7, mt = lane >> 3;
    const int m0 = warp * 16;

    const size_t bh = (size_t)(b * NH + h) * SEQ * HD;
    const __half* Qp = g_q16 + bh;
    const __half* Kp = g_k16 + bh;
    const __half* Vp = g_v16 + bh;

    const uint32_t q_sm = smem_u32(Qs);
    const uint32_t k_sm = smem_u32(Ks);
    const uint32_t v_sm = smem_u32(Vs);

    // stage Q (128 rows x 64 halves = 1024 chunks, 4/thread)
    #pragma unroll
    for (int p = 0; p < 4; p++) {
        int c = tid + p * 256;
        int row = c >> 3, cc = c & 7;
        CP16(q_sm + (row * SQ + cc * 8) * 2,
             Qp + (size_t)(q0 + row) * HD + cc * 8);
    }
    auto stageKV = [&](int s, int kt) {
        #pragma unroll
        for (int p = 0; p < 2; p++) {
            int c = tid + p * 256;
            int row = c >> 3, cc = c & 7;
            const size_t go = (size_t)(kt * 64 + row) * HD + cc * 8;
            CP16(k_sm + (s * KBUF + row * SQ + cc * 8) * 2, Kp + go);
            CP16(v_sm + (s * KBUF + row * SQ + cc * 8) * 2, Vp + go);
        }
    };
    stageKV(0, 0);
    CP_COMMIT();

    float oacc[8][4];
    #pragma unroll
    for (int j = 0; j < 8; j++)
        #pragma unroll
        for (int c = 0; c < 4; c++) oacc[j][c] = 0.f;
    float mrow0 = -1e30f, mrow1 = -1e30f, lrow0 = 0.f, lrow1 = 0.f;

    for (int kt = 0; kt < 32; kt++) {
        if (kt < 31) { stageKV((kt + 1) & 1, kt + 1); CP_COMMIT(); CP_WAIT1(); }
        else         { CP_WAIT0(); }
        __syncthreads();

        const uint32_t kb = k_sm + (kt & 1) * KBUF * 2;
        const uint32_t vb = v_sm + (kt & 1) * KBUF * 2;

        // ---- S = Q @ K^T ----
        float s_[8][4];
        #pragma unroll
        for (int j = 0; j < 8; j++)
            #pragma unroll
            for (int c = 0; c < 4; c++) s_[j][c] = 0.f;

        #pragma unroll
        for (int ks = 0; ks < 4; ks++) {
            const int k0 = ks * 16;
            uint32_t a[4];
            ldsm4(a, q_sm + ((m0 + (mt & 1) * 8 + r8) * SQ + k0 + (mt >> 1) * 8) * 2);
            #pragma unroll
            for (int j2 = 0; j2 < 4; j2++) {
                uint32_t bf[4];
                ldsm4(bf, kb + ((j2 * 16 + (mt >> 1) * 8 + r8) * SQ
                                + k0 + (mt & 1) * 8) * 2);
                mma16(s_[2 * j2],     a, &bf[0]);
                mma16(s_[2 * j2 + 1], a, &bf[2]);
            }
        }

        // ---- online softmax (scale 1/8 folded in) ----
        float tmax0 = -1e30f, tmax1 = -1e30f;
        #pragma unroll
        for (int j = 0; j < 8; j++) {
            s_[j][0] *= 0.125f; s_[j][1] *= 0.125f;
            s_[j][2] *= 0.125f; s_[j][3] *= 0.125f;
            tmax0 = fmaxf(tmax0, fmaxf(s_[j][0], s_[j][1]));
            tmax1 = fmaxf(tmax1, fmaxf(s_[j][2], s_[j][3]));
        }
        tmax0 = fmaxf(tmax0, __shfl_xor_sync(0xffffffffu, tmax0, 1));
        tmax0 = fmaxf(tmax0, __shfl_xor_sync(0xffffffffu, tmax0, 2));
        tmax1 = fmaxf(tmax1, __shfl_xor_sync(0xffffffffu, tmax1, 1));
        tmax1 = fmaxf(tmax1, __shfl_xor_sync(0xffffffffu, tmax1, 2));

        const float newm0 = fmaxf(mrow0, tmax0);
        const float newm1 = fmaxf(mrow1, tmax1);
        const float alpha0 = __expf(mrow0 - newm0);
        const float alpha1 = __expf(mrow1 - newm1);

        float sum0 = 0.f, sum1 = 0.f;
        #pragma unroll
        for (int j = 0; j < 8; j++) {
            s_[j][0] = __expf(s_[j][0] - newm0);
            s_[j][1] = __expf(s_[j][1] - newm0);
            s_[j][2] = __expf(s_[j][2] - newm1);
            s_[j][3] = __expf(s_[j][3] - newm1);
            sum0 += s_[j][0] + s_[j][1];
            sum1 += s_[j][2] + s_[j][3];
        }
        sum0 += __shfl_xor_sync(0xffffffffu, sum0, 1);
        sum0 += __shfl_xor_sync(0xffffffffu, sum0, 2);
        sum1 += __shfl_xor_sync(0xffffffffu, sum1, 1);
        sum1 += __shfl_xor_sync(0xffffffffu, sum1, 2);

        lrow0 = lrow0 * alpha0 + sum0;
        lrow1 = lrow1 * alpha1 + sum1;
        mrow0 = newm0; mrow1 = newm1;

        #pragma unroll
        for (int j = 0; j < 8; j++) {
            oacc[j][0] *= alpha0; oacc[j][1] *= alpha0;
            oacc[j][2] *= alpha1; oacc[j][3] *= alpha1;
        }

        // ---- P in registers: C-frag layout == A-frag layout (half2 packed) ----
        uint32_t pa[4][4];
        #pragma unroll
        for (int ks2 = 0; ks2 < 4; ks2++) {
            pa[ks2][0] = packh2(s_[2 * ks2][0],     s_[2 * ks2][1]);
            pa[ks2][1] = packh2(s_[2 * ks2][2],     s_[2 * ks2][3]);
            pa[ks2][2] = packh2(s_[2 * ks2 + 1][0], s_[2 * ks2 + 1][1]);
            pa[ks2][3] = packh2(s_[2 * ks2 + 1][2], s_[2 * ks2 + 1][3]);
        }

        // ---- O += P @ V ----
        #pragma unroll
        for (int ks2 = 0; ks2 < 4; ks2++) {
            const int k0 = ks2 * 16;
            #pragma unroll
            for (int j2 = 0; j2 < 4; j2++) {
                uint32_t bf[4];
                ldsm4t(bf, vb + ((k0 + (mt & 1) * 8 + r8) * SQ
                                 + j2 * 16 + (mt >> 1) * 8) * 2);
                mma16(oacc[2 * j2],     pa[ks2], &bf[0]);
                mma16(oacc[2 * j2 + 1], pa[ks2], &bf[2]);
            }
        }
        __syncthreads();
    }

    // ---- write O (normalized, fp16) in [B,S,E] layout ----
    const float inv0 = 1.f / lrow0;
    const float inv1 = 1.f / lrow1;
    const int row0 = q0 + m0 + g;
    const int row1 = row0 + 8;
    __half* dst0 = g_o16 + (size_t)(b * SEQ + row0) * EMB + h * HD;
    __half* dst1 = g_o16 + (size_t)(b * SEQ + row1) * EMB + h * HD;
    #pragma unroll
    for (int j = 0; j < 8; j++) {
        const int col = j * 8 + 2 * t4;
        *(__half2*)(dst0 + col) = __floats2half2_rn(oacc[j][0] * inv0, oacc[j][1] * inv0);
        *(__half2*)(dst1 + col) = __floats2half2_rn(oacc[j][2] * inv1, oacc[j][3] * inv1);
    }
}

// ---------------------------------------------------------------------------
extern "C" void kernel_launch(void* const* d_in, const int* in_sizes, int n_in,
                              void* d_out, int out_size)
{
    const float* x      = (const float*)d_in[0];
    const float* w_qkv  = (const float*)d_in[1];
    const float* b_qkv  = (const float*)d_in[2];
    const float* w_proj = (const float*)d_in[3];
    const float* b_proj = (const float*)d_in[4];
    float* out = (float*)d_out;

    __half *p_x16, *p_w16, *p_wp16, *p_o16;
    cudaGetSymbolAddress((void**)&p_x16,  gx16);
    cudaGetSymbolAddress((void**)&p_w16,  gw16);
    cudaGetSymbolAddress((void**)&p_wp16, gwp16);
    cudaGetSymbolAddress((void**)&p_o16,  g_o16);

    cudaFuncSetAttribute(attn_h, cudaFuncAttributeMaxDynamicSharedMemorySize, ATTN_SMEM);

    // 0) fp32 -> fp16 conversions
    cvt4<<<1024, 256>>>(x,      p_x16,  (MROWS * EMB) / 4);
    cvt4<<<1024, 256>>>(w_qkv,  p_w16,  (EMB * N_QKV) / 4);
    cvt4<<<512,  256>>>(w_proj, p_wp16, (EMB * EMB) / 4);

    // 1) QKV projection -> g_q16/g_k16/g_v16 [B,H,S,D]
    {
        dim3 grid(N_QKV / 128, MROWS / 128);
        gemm_h<0><<<grid, 256>>>(p_x16, p_w16, b_qkv, nullptr, N_QKV);
    }
    // 2) Attention -> g_o16 [B,S,E]
    {
        dim3 grid(SEQ / 128, NH, BATCH);
        attn_h<<<grid, 256, ATTN_SMEM>>>();
    }
    // 3) Output projection -> d_out (fp32)
    {
        dim3 grid(EMB / 128, MROWS / 128);
        gemm_h<1><<<grid, 256>>>(p_o16, p_wp16, b_proj, out, EMB);
    }
}

// round 5
// speedup vs baseline: 9.5387x; 1.1144x over previous
#include <cuda_runtime.h>
#include <cuda_fp16.h>
#include <math.h>
#include <stdint.h>

#define BATCH 4
#define SEQ   2048
#define EMB   1024
#define NH    16
#define HD    64
#define MROWS (BATCH*SEQ)     /* 8192 */
#define N_QKV (3*EMB)         /* 3072 */

// fp16 scratch (allocation-free rule: __device__ globals)
__device__ __half gx16[MROWS*EMB];
__device__ __half gw16[EMB*N_QKV];
__device__ __half gwp16[EMB*EMB];
__device__ __half g_q16[BATCH*NH*SEQ*HD];
__device__ __half g_k16[BATCH*NH*SEQ*HD];
__device__ __half g_v16[BATCH*NH*SEQ*HD];
__device__ __half g_o16[MROWS*EMB];

// ---------------------------------------------------------------------------
// helpers
// ---------------------------------------------------------------------------
__device__ __forceinline__ uint32_t smem_u32(const void* p) {
    uint32_t a;
    asm("{ .reg .u64 t; cvta.to.shared.u64 t, %1; cvt.u32.u64 %0, t; }"
        : "=r"(a) : "l"(p));
    return a;
}
#define CP16(dst, src) \
    asm volatile("cp.async.cg.shared.global [%0], [%1], 16;" :: "r"(dst), "l"(src))
#define CP_COMMIT() asm volatile("cp.async.commit_group;")
#define CP_WAIT0()  asm volatile("cp.async.wait_group 0;")
#define CP_WAIT1()  asm volatile("cp.async.wait_group 1;")

__device__ __forceinline__ void ldsm4(uint32_t* r, uint32_t addr) {
    asm volatile("ldmatrix.sync.aligned.m8n8.x4.shared.b16 {%0,%1,%2,%3}, [%4];"
        : "=r"(r[0]), "=r"(r[1]), "=r"(r[2]), "=r"(r[3]) : "r"(addr));
}
__device__ __forceinline__ void ldsm4t(uint32_t* r, uint32_t addr) {
    asm volatile("ldmatrix.sync.aligned.m8n8.x4.trans.shared.b16 {%0,%1,%2,%3}, [%4];"
        : "=r"(r[0]), "=r"(r[1]), "=r"(r[2]), "=r"(r[3]) : "r"(addr));
}
__device__ __forceinline__ void mma16(float* c, const uint32_t* a, const uint32_t* b) {
    asm volatile(
        "mma.sync.aligned.m16n8k16.row.col.f32.f16.f16.f32 "
        "{%0,%1,%2,%3},{%4,%5,%6,%7},{%8,%9},{%0,%1,%2,%3};\n"
        : "+f"(c[0]), "+f"(c[1]), "+f"(c[2]), "+f"(c[3])
        : "r"(a[0]), "r"(a[1]), "r"(a[2]), "r"(a[3]), "r"(b[0]), "r"(b[1]));
}
__device__ __forceinline__ uint32_t packh2(float x, float y) {
    __half2 h = __floats2half2_rn(x, y);
    return *(uint32_t*)&h;
}

// ---------------------------------------------------------------------------
// fp32 -> fp16 conversion (grid-stride over float4)
// ---------------------------------------------------------------------------
__global__ void cvt4(const float* __restrict__ src, __half* __restrict__ dst, int n4)
{
    for (int i = blockIdx.x * blockDim.x + threadIdx.x; i < n4; i += gridDim.x * blockDim.x) {
        float4 v = *(const float4*)(src + 4 * i);
        uint2 o;
        o.x = packh2(v.x, v.y);
        o.y = packh2(v.z, v.w);
        *(uint2*)(dst + 4 * i) = o;
    }
}

// ---------------------------------------------------------------------------
// fp16 HMMA GEMM: C[M,N] = A[M,1024] @ W[1024,N] + bias
// BM=128, BN=128, BK=32, 128 threads (4 warps, 2x2), warp tile 64x64,
// cp.async double-buffered. 2 CTAs/SM.
// MODE 0: scatter fp16 into g_q16/g_k16/g_v16 [B,H,S,D]; MODE 1: fp32 store.
// ---------------------------------------------------------------------------
#define SA 40
#define SB 136
#define ABUF (128*SA)   /* halves per A buffer */
#define BBUF (32*SB)

template<int MODE>
__global__ __launch_bounds__(128, 2)
void gemm_h(const __half* __restrict__ Ag,
            const __half* __restrict__ W,
            const float* __restrict__ bias,
            float* __restrict__ C,
            int N)
{
    __shared__ __half As[2][ABUF];
    __shared__ __half Bs[2][BBUF];

    const int tid  = threadIdx.x;
    const int warp = tid >> 5, lane = tid & 31;
    const int g = lane >> 2, t4 = lane & 3;
    const int r8 = lane & 7, mt = lane >> 3;
    const int wm = (warp >> 1) * 64, wn = (warp & 1) * 64;
    const int bx = blockIdx.x, by = blockIdx.y;

    const __half* Ab = Ag + (size_t)(by * 128) * 1024;
    const __half* Wb = W + bx * 128;

    const uint32_t a_sm = smem_u32(&As[0][0]);
    const uint32_t b_sm = smem_u32(&Bs[0][0]);

    float acc[4][8][4];
    #pragma unroll
    for (int i = 0; i < 4; i++)
        #pragma unroll
        for (int j = 0; j < 8; j++)
            #pragma unroll
            for (int c = 0; c < 4; c++) acc[i][j][c] = 0.f;

    // ---- stage tile kt into buffer s ----
    auto stage = [&](int s, int kt) {
        #pragma unroll
        for (int p = 0; p < 4; p++) {
            int c = tid + p * 128;
            int row = c >> 2, cc = c & 3;
            const __half* src = Ab + (size_t)row * 1024 + kt * 32 + cc * 8;
            CP16(a_sm + (s * ABUF + row * SA + cc * 8) * 2, src);
        }
        #pragma unroll
        for (int p = 0; p < 4; p++) {
            int c = tid + p * 128;
            int kr = c >> 4, nc = c & 15;
            const __half* src = Wb + (size_t)(kt * 32 + kr) * N + nc * 8;
            CP16(b_sm + (s * BBUF + kr * SB + nc * 8) * 2, src);
        }
    };

    stage(0, 0);
    CP_COMMIT();

    for (int kt = 0; kt < 32; kt++) {
        if (kt < 31) { stage((kt + 1) & 1, kt + 1); CP_COMMIT(); CP_WAIT1(); }
        else         { CP_WAIT0(); }
        __syncthreads();

        const int s = kt & 1;
        const uint32_t ab = a_sm + s * ABUF * 2;
        const uint32_t bb = b_sm + s * BBUF * 2;
        #pragma unroll
        for (int ks = 0; ks < 2; ks++) {
            const int k0 = ks * 16;
            uint32_t a[4][4];
            #pragma unroll
            for (int i = 0; i < 4; i++)
                ldsm4(a[i], ab + ((wm + i * 16 + (mt & 1) * 8 + r8) * SA
                                  + k0 + (mt >> 1) * 8) * 2);
            uint32_t b[4][4];
            #pragma unroll
            for (int j2 = 0; j2 < 4; j2++)
                ldsm4t(b[j2], bb + ((k0 + (mt & 1) * 8 + r8) * SB
                                    + wn + j2 * 16 + (mt >> 1) * 8) * 2);
            #pragma unroll
            for (int i = 0; i < 4; i++)
                #pragma unroll
                for (int j = 0; j < 8; j++)
                    mma16(acc[i][j], a[i], &b[j >> 1][(j & 1) * 2]);
        }
        __syncthreads();
    }

    // ---- epilogue ----
    #pragma unroll
    for (int i = 0; i < 4; i++) {
        #pragma unroll
        for (int j = 0; j < 8; j++) {
            const int m = by * 128 + wm + i * 16 + g;
            const int n = bx * 128 + wn + j * 8 + 2 * t4;
            const float bn0 = bias[n], bn1 = bias[n + 1];
            float v00 = acc[i][j][0] + bn0, v01 = acc[i][j][1] + bn1;  // row m
            float v10 = acc[i][j][2] + bn0, v11 = acc[i][j][3] + bn1;  // row m+8
            if (MODE == 0) {
                const int cls = n >> 10, rr = n & 1023;
                const int hh = rr >> 6, d = rr & 63;
                __half* base = (cls == 0) ? g_q16 : (cls == 1) ? g_k16 : g_v16;
                const int b0 = m >> 11, s0 = m & 2047;
                const int b1 = (m + 8) >> 11, s1 = (m + 8) & 2047;
                __half2 h0 = __floats2half2_rn(v00, v01);
                __half2 h1 = __floats2half2_rn(v10, v11);
                *(__half2*)(base + ((size_t)(b0 * NH + hh) * SEQ + s0) * HD + d) = h0;
                *(__half2*)(base + ((size_t)(b1 * NH + hh) * SEQ + s1) * HD + d) = h1;
            } else {
                float2 f0 = make_float2(v00, v01);
                float2 f1 = make_float2(v10, v11);
                *(float2*)(C + (size_t)m * N + n) = f0;
                *(float2*)(C + (size_t)(m + 8) * N + n) = f1;
            }
        }
    }
}

// ---------------------------------------------------------------------------
// fp16 flash attention. 128 threads (4 warps), q-tile 128 (32 rows/warp as
// two m16 tiles), kv-tile 64, cp.async double-buffered K/V, register P.
// ---------------------------------------------------------------------------
#define SQ 72
#define KBUF (64*SQ)
#define ATTN_SMEM ((128*SQ + 4*KBUF) * 2)   /* bytes = 55296 */

__global__ __launch_bounds__(128, 2)
void attn_h()
{
    extern __shared__ __half smh[];
    __half* Qs = smh;                 // 128 x SQ
    __half* Ks = Qs + 128 * SQ;       // 2 x 64 x SQ
    __half* Vs = Ks + 2 * KBUF;       // 2 x 64 x SQ

    const int b = blockIdx.z;
    const int h = blockIdx.y;
    const int q0 = blockIdx.x * 128;

    const int tid  = threadIdx.x;
    const int warp = tid >> 5, lane = tid & 31;
    const int g = lane >> 2, t4 = lane & 3;
    const int r8 = lane & 7, mt = lane >> 3;
    const int m0 = warp * 32;

    const size_t bh = (size_t)(b * NH + h) * SEQ * HD;
    const __half* Qp = g_q16 + bh;
    const __half* Kp = g_k16 + bh;
    const __half* Vp = g_v16 + bh;

    const uint32_t q_sm = smem_u32(Qs);
    const uint32_t k_sm = smem_u32(Ks);
    const uint32_t v_sm = smem_u32(Vs);

    // stage Q (128 rows x 64 halves = 1024 chunks, 8/thread)
    #pragma unroll
    for (int p = 0; p < 8; p++) {
        int c = tid + p * 128;
        int row = c >> 3, cc = c & 7;
        CP16(q_sm + (row * SQ + cc * 8) * 2,
             Qp + (size_t)(q0 + row) * HD + cc * 8);
    }
    auto stageKV = [&](int s, int kt) {
        #pragma unroll
        for (int p = 0; p < 4; p++) {
            int c = tid + p * 128;
            int row = c >> 3, cc = c & 7;
            const size_t go = (size_t)(kt * 64 + row) * HD + cc * 8;
            CP16(k_sm + (s * KBUF + row * SQ + cc * 8) * 2, Kp + go);
            CP16(v_sm + (s * KBUF + row * SQ + cc * 8) * 2, Vp + go);
        }
    };
    stageKV(0, 0);
    CP_COMMIT();

    float oacc[2][8][4];
    #pragma unroll
    for (int t = 0; t < 2; t++)
        #pragma unroll
        for (int j = 0; j < 8; j++)
            #pragma unroll
            for (int c = 0; c < 4; c++) oacc[t][j][c] = 0.f;
    float mrow0[2] = {-1e30f, -1e30f}, mrow1[2] = {-1e30f, -1e30f};
    float lrow0[2] = {0.f, 0.f},       lrow1[2] = {0.f, 0.f};

    for (int kt = 0; kt < 32; kt++) {
        if (kt < 31) { stageKV((kt + 1) & 1, kt + 1); CP_COMMIT(); CP_WAIT1(); }
        else         { CP_WAIT0(); }
        __syncthreads();

        const uint32_t kb = k_sm + (kt & 1) * KBUF * 2;
        const uint32_t vb = v_sm + (kt & 1) * KBUF * 2;

        // ---- S = Q @ K^T (two m16 tiles per warp) ----
        float s_[2][8][4];
        #pragma unroll
        for (int t = 0; t < 2; t++)
            #pragma unroll
            for (int j = 0; j < 8; j++)
                #pragma unroll
                for (int c = 0; c < 4; c++) s_[t][j][c] = 0.f;

        #pragma unroll
        for (int ks = 0; ks < 4; ks++) {
            const int k0 = ks * 16;
            uint32_t a[2][4];
            #pragma unroll
            for (int t = 0; t < 2; t++)
                ldsm4(a[t], q_sm + ((m0 + t * 16 + (mt & 1) * 8 + r8) * SQ
                                    + k0 + (mt >> 1) * 8) * 2);
            #pragma unroll
            for (int j2 = 0; j2 < 4; j2++) {
                uint32_t bf[4];
                ldsm4(bf, kb + ((j2 * 16 + (mt >> 1) * 8 + r8) * SQ
                                + k0 + (mt & 1) * 8) * 2);
                #pragma unroll
                for (int t = 0; t < 2; t++) {
                    mma16(s_[t][2 * j2],     a[t], &bf[0]);
                    mma16(s_[t][2 * j2 + 1], a[t], &bf[2]);
                }
            }
        }

        // ---- online softmax + build P fragments ----
        uint32_t pa[2][4][4];
        #pragma unroll
        for (int t = 0; t < 2; t++) {
            float tmax0 = -1e30f, tmax1 = -1e30f;
            #pragma unroll
            for (int j = 0; j < 8; j++) {
                s_[t][j][0] *= 0.125f; s_[t][j][1] *= 0.125f;
                s_[t][j][2] *= 0.125f; s_[t][j][3] *= 0.125f;
                tmax0 = fmaxf(tmax0, fmaxf(s_[t][j][0], s_[t][j][1]));
                tmax1 = fmaxf(tmax1, fmaxf(s_[t][j][2], s_[t][j][3]));
            }
            tmax0 = fmaxf(tmax0, __shfl_xor_sync(0xffffffffu, tmax0, 1));
            tmax0 = fmaxf(tmax0, __shfl_xor_sync(0xffffffffu, tmax0, 2));
            tmax1 = fmaxf(tmax1, __shfl_xor_sync(0xffffffffu, tmax1, 1));
            tmax1 = fmaxf(tmax1, __shfl_xor_sync(0xffffffffu, tmax1, 2));

            const float newm0 = fmaxf(mrow0[t], tmax0);
            const float newm1 = fmaxf(mrow1[t], tmax1);
            const float alpha0 = __expf(mrow0[t] - newm0);
            const float alpha1 = __expf(mrow1[t] - newm1);

            float sum0 = 0.f, sum1 = 0.f;
            #pragma unroll
            for (int j = 0; j < 8; j++) {
                s_[t][j][0] = __expf(s_[t][j][0] - newm0);
                s_[t][j][1] = __expf(s_[t][j][1] - newm0);
                s_[t][j][2] = __expf(s_[t][j][2] - newm1);
                s_[t][j][3] = __expf(s_[t][j][3] - newm1);
                sum0 += s_[t][j][0] + s_[t][j][1];
                sum1 += s_[t][j][2] + s_[t][j][3];
            }
            sum0 += __shfl_xor_sync(0xffffffffu, sum0, 1);
            sum0 += __shfl_xor_sync(0xffffffffu, sum0, 2);
            sum1 += __shfl_xor_sync(0xffffffffu, sum1, 1);
            sum1 += __shfl_xor_sync(0xffffffffu, sum1, 2);

            lrow0[t] = lrow0[t] * alpha0 + sum0;
            lrow1[t] = lrow1[t] * alpha1 + sum1;
            mrow0[t] = newm0; mrow1[t] = newm1;

            #pragma unroll
            for (int j = 0; j < 8; j++) {
                oacc[t][j][0] *= alpha0; oacc[t][j][1] *= alpha0;
                oacc[t][j][2] *= alpha1; oacc[t][j][3] *= alpha1;
            }
            #pragma unroll
            for (int ks2 = 0; ks2 < 4; ks2++) {
                pa[t][ks2][0] = packh2(s_[t][2 * ks2][0],     s_[t][2 * ks2][1]);
                pa[t][ks2][1] = packh2(s_[t][2 * ks2][2],     s_[t][2 * ks2][3]);
                pa[t][ks2][2] = packh2(s_[t][2 * ks2 + 1][0], s_[t][2 * ks2 + 1][1]);
                pa[t][ks2][3] = packh2(s_[t][2 * ks2 + 1][2], s_[t][2 * ks2 + 1][3]);
            }
        }

        // ---- O += P @ V (V fragments shared across both m16 tiles) ----
        #pragma unroll
        for (int ks2 = 0; ks2 < 4; ks2++) {
            const int k0 = ks2 * 16;
            #pragma unroll
            for (int j2 = 0; j2 < 4; j2++) {
                uint32_t bf[4];
                ldsm4t(bf, vb + ((k0 + (mt & 1) * 8 + r8) * SQ
                                 + j2 * 16 + (mt >> 1) * 8) * 2);
                #pragma unroll
                for (int t = 0; t < 2; t++) {
                    mma16(oacc[t][2 * j2],     pa[t][ks2], &bf[0]);
                    mma16(oacc[t][2 * j2 + 1], pa[t][ks2], &bf[2]);
                }
            }
        }
        __syncthreads();
    }

    // ---- write O (normalized, fp16) in [B,S,E] layout ----
    #pragma unroll
    for (int t = 0; t < 2; t++) {
        const float inv0 = 1.f / lrow0[t];
        const float inv1 = 1.f / lrow1[t];
        const int row0 = q0 + m0 + t * 16 + g;
        const int row1 = row0 + 8;
        __half* dst0 = g_o16 + (size_t)(b * SEQ + row0) * EMB + h * HD;
        __half* dst1 = g_o16 + (size_t)(b * SEQ + row1) * EMB + h * HD;
        #pragma unroll
        for (int j = 0; j < 8; j++) {
            const int col = j * 8 + 2 * t4;
            *(__half2*)(dst0 + col) = __floats2half2_rn(oacc[t][j][0] * inv0,
                                                        oacc[t][j][1] * inv0);
            *(__half2*)(dst1 + col) = __floats2half2_rn(oacc[t][j][2] * inv1,
                                                        oacc[t][j][3] * inv1);
        }
    }
}

// ---------------------------------------------------------------------------
extern "C" void kernel_launch(void* const* d_in, const int* in_sizes, int n_in,
                              void* d_out, int out_size)
{
    const float* x      = (const float*)d_in[0];
    const float* w_qkv  = (const float*)d_in[1];
    const float* b_qkv  = (const float*)d_in[2];
    const float* w_proj = (const float*)d_in[3];
    const float* b_proj = (const float*)d_in[4];
    float* out = (float*)d_out;

    __half *p_x16, *p_w16, *p_wp16, *p_o16;
    cudaGetSymbolAddress((void**)&p_x16,  gx16);
    cudaGetSymbolAddress((void**)&p_w16,  gw16);
    cudaGetSymbolAddress((void**)&p_wp16, gwp16);
    cudaGetSymbolAddress((void**)&p_o16,  g_o16);

    cudaFuncSetAttribute(attn_h, cudaFuncAttributeMaxDynamicSharedMemorySize, ATTN_SMEM);

    // 0) fp32 -> fp16 conversions
    cvt4<<<1024, 256>>>(x,      p_x16,  (MROWS * EMB) / 4);
    cvt4<<<1024, 256>>>(w_qkv,  p_w16,  (EMB * N_QKV) / 4);
    cvt4<<<512,  256>>>(w_proj, p_wp16, (EMB * EMB) / 4);

    // 1) QKV projection -> g_q16/g_k16/g_v16 [B,H,S,D]
    {
        dim3 grid(N_QKV / 128, MROWS / 128);
        gemm_h<0><<<grid, 128>>>(p_x16, p_w16, b_qkv, nullptr, N_QKV);
    }
    // 2) Attention -> g_o16 [B,S,E]
    {
        dim3 grid(SEQ / 128, NH, BATCH);
        attn_h<<<grid, 128, ATTN_SMEM>>>();
    }
    // 3) Output projection -> d_out (fp32)
    {
        dim3 grid(EMB / 128, MROWS / 128);
        gemm_h<1><<<grid, 128>>>(p_o16, p_wp16, b_proj, out, EMB);
    }
}

// round 6
// speedup vs baseline: 9.9350x; 1.0415x over previous
#include <cuda_runtime.h>
#include <cuda_fp16.h>
#include <math.h>
#include <stdint.h>

#define BATCH 4
#define SEQ   2048
#define EMB   1024
#define NH    16
#define HD    64
#define MROWS (BATCH*SEQ)     /* 8192 */
#define N_QKV (3*EMB)         /* 3072 */

// Q pre-scale: 1/sqrt(64) * log2(e)
#define QSCALE 0.18033688011112042f

// fp16 scratch (allocation-free rule: __device__ globals)
__device__ __half gx16[MROWS*EMB];
__device__ __half gw16[EMB*N_QKV];
__device__ __half gwp16[EMB*EMB];
__device__ __half gqkv16[MROWS*N_QKV];   // row-major QKV output
__device__ __half g_o16[MROWS*EMB];

// ---------------------------------------------------------------------------
// helpers
// ---------------------------------------------------------------------------
__device__ __forceinline__ uint32_t smem_u32(const void* p) {
    uint32_t a;
    asm("{ .reg .u64 t; cvta.to.shared.u64 t, %1; cvt.u32.u64 %0, t; }"
        : "=r"(a) : "l"(p));
    return a;
}
#define CP16(dst, src) \
    asm volatile("cp.async.cg.shared.global [%0], [%1], 16;" :: "r"(dst), "l"(src))
#define CP_COMMIT() asm volatile("cp.async.commit_group;")
#define CP_WAIT0()  asm volatile("cp.async.wait_group 0;")
#define CP_WAIT1()  asm volatile("cp.async.wait_group 1;")

__device__ __forceinline__ void ldsm4(uint32_t* r, uint32_t addr) {
    asm volatile("ldmatrix.sync.aligned.m8n8.x4.shared.b16 {%0,%1,%2,%3}, [%4];"
        : "=r"(r[0]), "=r"(r[1]), "=r"(r[2]), "=r"(r[3]) : "r"(addr));
}
__device__ __forceinline__ void ldsm4t(uint32_t* r, uint32_t addr) {
    asm volatile("ldmatrix.sync.aligned.m8n8.x4.trans.shared.b16 {%0,%1,%2,%3}, [%4];"
        : "=r"(r[0]), "=r"(r[1]), "=r"(r[2]), "=r"(r[3]) : "r"(addr));
}
__device__ __forceinline__ void mma16(float* c, const uint32_t* a, const uint32_t* b) {
    asm volatile(
        "mma.sync.aligned.m16n8k16.row.col.f32.f16.f16.f32 "
        "{%0,%1,%2,%3},{%4,%5,%6,%7},{%8,%9},{%0,%1,%2,%3};\n"
        : "+f"(c[0]), "+f"(c[1]), "+f"(c[2]), "+f"(c[3])
        : "r"(a[0]), "r"(a[1]), "r"(a[2]), "r"(a[3]), "r"(b[0]), "r"(b[1]));
}
__device__ __forceinline__ uint32_t packh2(float x, float y) {
    __half2 h = __floats2half2_rn(x, y);
    return *(uint32_t*)&h;
}
__device__ __forceinline__ float ex2(float x) {
    float y;
    asm("ex2.approx.f32 %0, %1;" : "=f"(y) : "f"(x));
    return y;
}

// ---------------------------------------------------------------------------
// fp32 -> fp16 conversion (grid-stride over float4)
// ---------------------------------------------------------------------------
__global__ void cvt4(const float* __restrict__ src, __half* __restrict__ dst, int n4)
{
    for (int i = blockIdx.x * blockDim.x + threadIdx.x; i < n4; i += gridDim.x * blockDim.x) {
        float4 v = *(const float4*)(src + 4 * i);
        uint2 o;
        o.x = packh2(v.x, v.y);
        o.y = packh2(v.z, v.w);
        *(uint2*)(dst + 4 * i) = o;
    }
}

// ---------------------------------------------------------------------------
// fp16 HMMA GEMM: BM=128, BN=128, BK=32, 128 threads (4 warps 2x2),
// warp tile 64x64, 3-stage cp.async ring, ONE syncthreads per k-tile.
// MODE 0: store fp16 row-major into C16 (Q cols pre-scaled by QSCALE)
// MODE 1: store fp32 into C32.
// ---------------------------------------------------------------------------
#define SA 40
#define SB 136
#define ABUF (128*SA)   /* halves per A stage: 5120 */
#define BBUF (32*SB)    /* halves per B stage: 4352 */
#define GSMEM ((3*ABUF + 3*BBUF) * 2)   /* 56832 bytes */

template<int MODE>
__global__ __launch_bounds__(128, 2)
void gemm_h(const __half* __restrict__ Ag,
            const __half* __restrict__ W,
            const float* __restrict__ bias,
            float* __restrict__ C32,
            __half* __restrict__ C16,
            int N)
{
    extern __shared__ __half smg[];
    const uint32_t a_sm = smem_u32(smg);                 // 3 A stages
    const uint32_t b_sm = a_sm + 3 * ABUF * 2;           // 3 B stages

    const int tid  = threadIdx.x;
    const int warp = tid >> 5, lane = tid & 31;
    const int g = lane >> 2, t4 = lane & 3;
    const int r8 = lane & 7, mt = lane >> 3;
    const int wm = (warp >> 1) * 64, wn = (warp & 1) * 64;
    const int bx = blockIdx.x, by = blockIdx.y;

    const __half* Ab = Ag + (size_t)(by * 128) * 1024;
    const __half* Wb = W + bx * 128;

    float acc[4][8][4];
    #pragma unroll
    for (int i = 0; i < 4; i++)
        #pragma unroll
        for (int j = 0; j < 8; j++)
            #pragma unroll
            for (int c = 0; c < 4; c++) acc[i][j][c] = 0.f;

    auto stage = [&](int s, int kt) {
        #pragma unroll
        for (int p = 0; p < 4; p++) {
            int c = tid + p * 128;
            int row = c >> 2, cc = c & 3;
            CP16(a_sm + (s * ABUF + row * SA + cc * 8) * 2,
                 Ab + (size_t)row * 1024 + kt * 32 + cc * 8);
        }
        #pragma unroll
        for (int p = 0; p < 4; p++) {
            int c = tid + p * 128;
            int kr = c >> 4, nc = c & 15;
            CP16(b_sm + (s * BBUF + kr * SB + nc * 8) * 2,
                 Wb + (size_t)(kt * 32 + kr) * N + nc * 8);
        }
    };

    stage(0, 0); CP_COMMIT();
    stage(1, 1); CP_COMMIT();

    int sIdx = 0;                         // kt % 3
    for (int kt = 0; kt < 32; kt++) {
        if (kt == 31) { CP_WAIT0(); } else { CP_WAIT1(); }
        __syncthreads();
        if (kt < 30) {
            int s2 = sIdx + 2; if (s2 >= 3) s2 -= 3;
            stage(s2, kt + 2); CP_COMMIT();
        }

        const uint32_t ab = a_sm + sIdx * ABUF * 2;
        const uint32_t bb = b_sm + sIdx * BBUF * 2;
        #pragma unroll
        for (int ks = 0; ks < 2; ks++) {
            const int k0 = ks * 16;
            uint32_t a[4][4];
            #pragma unroll
            for (int i = 0; i < 4; i++)
                ldsm4(a[i], ab + ((wm + i * 16 + (mt & 1) * 8 + r8) * SA
                                  + k0 + (mt >> 1) * 8) * 2);
            uint32_t b[4][4];
            #pragma unroll
            for (int j2 = 0; j2 < 4; j2++)
                ldsm4t(b[j2], bb + ((k0 + (mt & 1) * 8 + r8) * SB
                                    + wn + j2 * 16 + (mt >> 1) * 8) * 2);
            #pragma unroll
            for (int i = 0; i < 4; i++)
                #pragma unroll
                for (int j = 0; j < 8; j++)
                    mma16(acc[i][j], a[i], &b[j >> 1][(j & 1) * 2]);
        }
        if (++sIdx >= 3) sIdx -= 3;
    }

    // ---- epilogue ----
    #pragma unroll
    for (int i = 0; i < 4; i++) {
        #pragma unroll
        for (int j = 0; j < 8; j++) {
            const int m = by * 128 + wm + i * 16 + g;
            const int n = bx * 128 + wn + j * 8 + 2 * t4;
            const float bn0 = bias[n], bn1 = bias[n + 1];
            float v00 = acc[i][j][0] + bn0, v01 = acc[i][j][1] + bn1;  // row m
            float v10 = acc[i][j][2] + bn0, v11 = acc[i][j][3] + bn1;  // row m+8
            if (MODE == 0) {
                if (n < EMB) {       // Q columns: fold softmax scale * log2e
                    v00 *= QSCALE; v01 *= QSCALE;
                    v10 *= QSCALE; v11 *= QSCALE;
                }
                *(__half2*)(C16 + (size_t)m * N + n)       = __floats2half2_rn(v00, v01);
                *(__half2*)(C16 + (size_t)(m + 8) * N + n) = __floats2half2_rn(v10, v11);
            } else {
                *(float2*)(C32 + (size_t)m * N + n)       = make_float2(v00, v01);
                *(float2*)(C32 + (size_t)(m + 8) * N + n) = make_float2(v10, v11);
            }
        }
    }
}

// ---------------------------------------------------------------------------
// fp16 flash attention reading strided Q/K/V columns from row-major QKV.
// 128 threads (4 warps), q-tile 128 (32 rows/warp), kv-tile 64,
// 3-stage KV ring, ONE syncthreads per kv-tile, base-2 softmax, register P.
// ---------------------------------------------------------------------------
#define SQ 72
#define KSTG (64*SQ)                    /* halves per K (or V) stage: 4608 */
#define QOFF (128*SQ)                   /* 9216 halves */
#define ATTN_SMEM ((QOFF + 6*KSTG) * 2) /* 73728 bytes */

__global__ __launch_bounds__(128, 2)
void attn_h()
{
    extern __shared__ __half smh[];
    const uint32_t q_sm = smem_u32(smh);
    const uint32_t k_sm = q_sm + QOFF * 2;
    const uint32_t v_sm = k_sm + 3 * KSTG * 2;

    const int b = blockIdx.z;
    const int h = blockIdx.y;
    const int q0 = blockIdx.x * 128;

    const int tid  = threadIdx.x;
    const int warp = tid >> 5, lane = tid & 31;
    const int g = lane >> 2, t4 = lane & 3;
    const int r8 = lane & 7, mt = lane >> 3;
    const int m0 = warp * 32;

    const __half* QKV = gqkv16;
    const size_t rowB = (size_t)b * SEQ;          // batch row offset
    const __half* Qp = QKV + (rowB + q0) * N_QKV + h * HD;
    const __half* Kp = QKV + rowB * N_QKV + EMB + h * HD;
    const __half* Vp = QKV + rowB * N_QKV + 2 * EMB + h * HD;

    // stage Q (128 rows x 64 halves), group 0 together with KV tile 0
    #pragma unroll
    for (int p = 0; p < 8; p++) {
        int c = tid + p * 128;
        int row = c >> 3, cc = c & 7;
        CP16(q_sm + (row * SQ + cc * 8) * 2, Qp + (size_t)row * N_QKV + cc * 8);
    }
    auto stageKV = [&](int s, int kt) {
        #pragma unroll
        for (int p = 0; p < 4; p++) {
            int c = tid + p * 128;
            int row = c >> 3, cc = c & 7;
            const size_t go = (size_t)(kt * 64 + row) * N_QKV + cc * 8;
            CP16(k_sm + (s * KSTG + row * SQ + cc * 8) * 2, Kp + go);
            CP16(v_sm + (s * KSTG + row * SQ + cc * 8) * 2, Vp + go);
        }
    };
    stageKV(0, 0); CP_COMMIT();
    stageKV(1, 1); CP_COMMIT();

    float oacc[2][8][4];
    #pragma unroll
    for (int t = 0; t < 2; t++)
        #pragma unroll
        for (int j = 0; j < 8; j++)
            #pragma unroll
            for (int c = 0; c < 4; c++) oacc[t][j][c] = 0.f;
    float mrow0[2] = {-1e30f, -1e30f}, mrow1[2] = {-1e30f, -1e30f};
    float lrow0[2] = {0.f, 0.f},       lrow1[2] = {0.f, 0.f};

    int sIdx = 0;
    for (int kt = 0; kt < 32; kt++) {
        if (kt == 31) { CP_WAIT0(); } else { CP_WAIT1(); }
        __syncthreads();
        if (kt < 30) {
            int s2 = sIdx + 2; if (s2 >= 3) s2 -= 3;
            stageKV(s2, kt + 2); CP_COMMIT();
        }

        const uint32_t kb = k_sm + sIdx * KSTG * 2;
        const uint32_t vb = v_sm + sIdx * KSTG * 2;

        // ---- S = Q @ K^T (two m16 tiles per warp); Q pre-scaled ----
        float s_[2][8][4];
        #pragma unroll
        for (int t = 0; t < 2; t++)
            #pragma unroll
            for (int j = 0; j < 8; j++)
                #pragma unroll
                for (int c = 0; c < 4; c++) s_[t][j][c] = 0.f;

        #pragma unroll
        for (int ks = 0; ks < 4; ks++) {
            const int k0 = ks * 16;
            uint32_t a[2][4];
            #pragma unroll
            for (int t = 0; t < 2; t++)
                ldsm4(a[t], q_sm + ((m0 + t * 16 + (mt & 1) * 8 + r8) * SQ
                                    + k0 + (mt >> 1) * 8) * 2);
            #pragma unroll
            for (int j2 = 0; j2 < 4; j2++) {
                uint32_t bf[4];
                ldsm4(bf, kb + ((j2 * 16 + (mt >> 1) * 8 + r8) * SQ
                                + k0 + (mt & 1) * 8) * 2);
                #pragma unroll
                for (int t = 0; t < 2; t++) {
                    mma16(s_[t][2 * j2],     a[t], &bf[0]);
                    mma16(s_[t][2 * j2 + 1], a[t], &bf[2]);
                }
            }
        }

        // ---- online softmax (base-2 domain) + build P fragments ----
        uint32_t pa[2][4][4];
        #pragma unroll
        for (int t = 0; t < 2; t++) {
            float tmax0 = -1e30f, tmax1 = -1e30f;
            #pragma unroll
            for (int j = 0; j < 8; j++) {
                tmax0 = fmaxf(tmax0, fmaxf(s_[t][j][0], s_[t][j][1]));
                tmax1 = fmaxf(tmax1, fmaxf(s_[t][j][2], s_[t][j][3]));
            }
            tmax0 = fmaxf(tmax0, __shfl_xor_sync(0xffffffffu, tmax0, 1));
            tmax0 = fmaxf(tmax0, __shfl_xor_sync(0xffffffffu, tmax0, 2));
            tmax1 = fmaxf(tmax1, __shfl_xor_sync(0xffffffffu, tmax1, 1));
            tmax1 = fmaxf(tmax1, __shfl_xor_sync(0xffffffffu, tmax1, 2));

            const float newm0 = fmaxf(mrow0[t], tmax0);
            const float newm1 = fmaxf(mrow1[t], tmax1);
            const float alpha0 = ex2(mrow0[t] - newm0);
            const float alpha1 = ex2(mrow1[t] - newm1);

            float sum0 = 0.f, sum1 = 0.f;
            #pragma unroll
            for (int j = 0; j < 8; j++) {
                s_[t][j][0] = ex2(s_[t][j][0] - newm0);
                s_[t][j][1] = ex2(s_[t][j][1] - newm0);
                s_[t][j][2] = ex2(s_[t][j][2] - newm1);
                s_[t][j][3] = ex2(s_[t][j][3] - newm1);
                sum0 += s_[t][j][0] + s_[t][j][1];
                sum1 += s_[t][j][2] + s_[t][j][3];
            }
            sum0 += __shfl_xor_sync(0xffffffffu, sum0, 1);
            sum0 += __shfl_xor_sync(0xffffffffu, sum0, 2);
            sum1 += __shfl_xor_sync(0xffffffffu, sum1, 1);
            sum1 += __shfl_xor_sync(0xffffffffu, sum1, 2);

            lrow0[t] = lrow0[t] * alpha0 + sum0;
            lrow1[t] = lrow1[t] * alpha1 + sum1;
            mrow0[t] = newm0; mrow1[t] = newm1;

            #pragma unroll
            for (int j = 0; j < 8; j++) {
                oacc[t][j][0] *= alpha0; oacc[t][j][1] *= alpha0;
                oacc[t][j][2] *= alpha1; oacc[t][j][3] *= alpha1;
            }
            #pragma unroll
            for (int ks2 = 0; ks2 < 4; ks2++) {
                pa[t][ks2][0] = packh2(s_[t][2 * ks2][0],     s_[t][2 * ks2][1]);
                pa[t][ks2][1] = packh2(s_[t][2 * ks2][2],     s_[t][2 * ks2][3]);
                pa[t][ks2][2] = packh2(s_[t][2 * ks2 + 1][0], s_[t][2 * ks2 + 1][1]);
                pa[t][ks2][3] = packh2(s_[t][2 * ks2 + 1][2], s_[t][2 * ks2 + 1][3]);
            }
        }

        // ---- O += P @ V (V fragments shared across both m16 tiles) ----
        #pragma unroll
        for (int ks2 = 0; ks2 < 4; ks2++) {
            const int k0 = ks2 * 16;
            #pragma unroll
            for (int j2 = 0; j2 < 4; j2++) {
                uint32_t bf[4];
                ldsm4t(bf, vb + ((k0 + (mt & 1) * 8 + r8) * SQ
                                 + j2 * 16 + (mt >> 1) * 8) * 2);
                #pragma unroll
                for (int t = 0; t < 2; t++) {
                    mma16(oacc[t][2 * j2],     pa[t][ks2], &bf[0]);
                    mma16(oacc[t][2 * j2 + 1], pa[t][ks2], &bf[2]);
                }
            }
        }
        if (++sIdx >= 3) sIdx -= 3;
    }

    // ---- write O (normalized, fp16) in [B,S,E] layout ----
    #pragma unroll
    for (int t = 0; t < 2; t++) {
        const float inv0 = 1.f / lrow0[t];
        const float inv1 = 1.f / lrow1[t];
        const int row0 = q0 + m0 + t * 16 + g;
        const int row1 = row0 + 8;
        __half* dst0 = g_o16 + (size_t)(b * SEQ + row0) * EMB + h * HD;
        __half* dst1 = g_o16 + (size_t)(b * SEQ + row1) * EMB + h * HD;
        #pragma unroll
        for (int j = 0; j < 8; j++) {
            const int col = j * 8 + 2 * t4;
            *(__half2*)(dst0 + col) = __floats2half2_rn(oacc[t][j][0] * inv0,
                                                        oacc[t][j][1] * inv0);
            *(__half2*)(dst1 + col) = __floats2half2_rn(oacc[t][j][2] * inv1,
                                                        oacc[t][j][3] * inv1);
        }
    }
}

// ---------------------------------------------------------------------------
extern "C" void kernel_launch(void* const* d_in, const int* in_sizes, int n_in,
                              void* d_out, int out_size)
{
    const float* x      = (const float*)d_in[0];
    const float* w_qkv  = (const float*)d_in[1];
    const float* b_qkv  = (const float*)d_in[2];
    const float* w_proj = (const float*)d_in[3];
    const float* b_proj = (const float*)d_in[4];
    float* out = (float*)d_out;

    __half *p_x16, *p_w16, *p_wp16, *p_qkv16, *p_o16;
    cudaGetSymbolAddress((void**)&p_x16,   gx16);
    cudaGetSymbolAddress((void**)&p_w16,   gw16);
    cudaGetSymbolAddress((void**)&p_wp16,  gwp16);
    cudaGetSymbolAddress((void**)&p_qkv16, gqkv16);
    cudaGetSymbolAddress((void**)&p_o16,   g_o16);

    cudaFuncSetAttribute(gemm_h<0>, cudaFuncAttributeMaxDynamicSharedMemorySize, GSMEM);
    cudaFuncSetAttribute(gemm_h<1>, cudaFuncAttributeMaxDynamicSharedMemorySize, GSMEM);
    cudaFuncSetAttribute(attn_h,    cudaFuncAttributeMaxDynamicSharedMemorySize, ATTN_SMEM);

    // 0) fp32 -> fp16 conversions
    cvt4<<<1024, 256>>>(x,      p_x16,  (MROWS * EMB) / 4);
    cvt4<<<1024, 256>>>(w_qkv,  p_w16,  (EMB * N_QKV) / 4);
    cvt4<<<512,  256>>>(w_proj, p_wp16, (EMB * EMB) / 4);

    // 1) QKV projection -> gqkv16 row-major [8192][3072] (Q cols pre-scaled)
    {
        dim3 grid(N_QKV / 128, MROWS / 128);
        gemm_h<0><<<grid, 128, GSMEM>>>(p_x16, p_w16, b_qkv, nullptr, p_qkv16, N_QKV);
    }
    // 2) Attention -> g_o16 [B,S,E]
    {
        dim3 grid(SEQ / 128, NH, BATCH);
        attn_h<<<grid, 128, ATTN_SMEM>>>();
    }
    // 3) Output projection -> d_out (fp32)
    {
        dim3 grid(EMB / 128, MROWS / 128);
        gemm_h<1><<<grid, 128, GSMEM>>>(p_o16, p_wp16, b_proj, out, nullptr, EMB);
    }
}